// round 14
// baseline (speedup 1.0000x reference)
#include <cuda_runtime.h>
#include <math.h>

#define H        128
#define B        256
#define WST      132      // fp32 stride: 132 % 32 == 4 -> conflict-free row+col access
#define SP       260      // packed float2 matrix stride (260 % 32 == 4)
#define PW       (2 * H + 8)
#define NCTA     128
#define NTHREADS 512
#define MAXIT    500
#define TOLF     1e-3f
#define PCTA     64       // precompute CTAs
#define PS       4        // samples per precompute CTA

// per-(iteration, CTA) residual slots; -1 = not posted, >=0 = posted value.
__device__ float g_part[65536];          // >= MAXIT*NCTA
// per-sample loop constants: [a0, c0, zur, a1, c1, a2w, vw2]
__device__ float g_c[7][B * H];

__device__ __forceinline__ float softplus_f(float s) {
    float e = __expf(s);
    float z = __logf(1.f + e);
    return (s > 15.f) ? s : z;
}

// ============================ precompute kernel ============================
// 64 CTAs x 4 samples. Each matrix staged coalesced into smem (double
// buffered against the previous matrix's smem matvec); every staged weight
// element feeds 4 FMAs (one per sample).

struct __align__(16) PSmem {
    float WB0[H * WST];
    float WB1[H * WST];
    float xv[PS][H];
    float u0[PS][H];
    float u1[PS][H];
    float P[4][PS][WST];      // [quarter][sample][h]
    float zu2[PS];
};

__device__ __forceinline__ void stage(float* dst, const float* __restrict__ w, int tid) {
#pragma unroll
    for (int i = 0; i < 8; i++) {
        int e = tid + i * 512;
        int r = e >> 5, c4 = (e & 31) * 4;
        *(float4*)&dst[r * WST + c4] = __ldg((const float4*)&w[r * H + c4]);
    }
}

// quarter matvec: smem weights row h seg [k0,k0+32) . four sample vectors
__device__ __forceinline__ void mvq4(const float* Wb, const float V[PS][H],
                                     float P[4][PS][WST], int q, int h, int k0) {
    const float4* W = (const float4*)&Wb[h * WST + k0];
    float m0 = 0.f, m1 = 0.f, m2 = 0.f, m3 = 0.f;
#pragma unroll
    for (int c = 0; c < 8; c++) {
        float4 w = W[c];
        float4 a = *(const float4*)&V[0][k0 + 4 * c];
        float4 b = *(const float4*)&V[1][k0 + 4 * c];
        float4 d = *(const float4*)&V[2][k0 + 4 * c];
        float4 e = *(const float4*)&V[3][k0 + 4 * c];
        m0 += w.x * a.x + w.y * a.y + w.z * a.z + w.w * a.w;
        m1 += w.x * b.x + w.y * b.y + w.z * b.z + w.w * b.w;
        m2 += w.x * d.x + w.y * d.y + w.z * d.z + w.w * d.w;
        m3 += w.x * e.x + w.y * e.y + w.z * e.z + w.w * e.w;
    }
    P[q][0][h] = m0;  P[q][1][h] = m1;
    P[q][2][h] = m2;  P[q][3][h] = m3;
}

__global__ __launch_bounds__(512, 1)
void pblnn_pre_kernel(
    const float* __restrict__ x,
    const float* __restrict__ wuu0_w, const float* __restrict__ wuu0_b,
    const float* __restrict__ wyu0_w, const float* __restrict__ wyu0_b,
    const float* __restrict__ wu0_w,  const float* __restrict__ wu0_b,
    const float* __restrict__ wuu1_w, const float* __restrict__ wuu1_b,
    const float* __restrict__ wzu1_w, const float* __restrict__ wzu1_b,
    const float* __restrict__ wyu1_w, const float* __restrict__ wyu1_b,
    const float* __restrict__ wu1_w,  const float* __restrict__ wu1_b,
    const float* __restrict__ wzu2_w, const float* __restrict__ wzu2_b,
    const float* __restrict__ wz2,
    const float* __restrict__ wyu2_w, const float* __restrict__ wyu2_b,
    const float* __restrict__ wy2)
{
    extern __shared__ char psm_raw[];
    PSmem& S = *reinterpret_cast<PSmem*>(psm_raw);

    const int tid = threadIdx.x;
    const int l   = tid & 31;
    const int wr  = tid >> 5;
    const int h   = tid & 127;
    const int q   = tid >> 7;          // quarter AND sample owned in combine
    const int k0  = q * 32;
    const int samp0 = blockIdx.x * PS;
    const int gi  = (samp0 + q) * H + h;

    // residual-slot init: 64*512*2 = 65536
    g_part[blockIdx.x * 512 + tid] = -1.f;
    g_part[blockIdx.x * 512 + tid + 32768] = -1.f;

    if (tid < PS * H) S.xv[tid >> 7][tid & 127] = x[samp0 * H + tid];
    stage(S.WB0, wuu0_w, tid);
    __syncthreads();

    // step 0: mv wuu0@x -> u0 ; stage wyu0
    stage(S.WB1, wyu0_w, tid);
    mvq4(S.WB0, S.xv, S.P, q, h, k0);
    __syncthreads();
    {
        float t = S.P[0][q][h] + S.P[1][q][h] + S.P[2][q][h] + S.P[3][q][h];
        S.u0[q][h] = softplus_f(t + wuu0_b[h]);
    }
    __syncthreads();

    // step 1: mv wyu0@x -> a0 ; stage wu0
    stage(S.WB0, wu0_w, tid);
    mvq4(S.WB1, S.xv, S.P, q, h, k0);
    __syncthreads();
    g_c[0][gi] = S.P[0][q][h] + S.P[1][q][h] + S.P[2][q][h] + S.P[3][q][h] + wyu0_b[h];
    __syncthreads();

    // step 2: mv wu0@x -> c0 ; stage wuu1
    stage(S.WB1, wuu1_w, tid);
    mvq4(S.WB0, S.xv, S.P, q, h, k0);
    __syncthreads();
    g_c[1][gi] = S.P[0][q][h] + S.P[1][q][h] + S.P[2][q][h] + S.P[3][q][h] + wu0_b[h];
    __syncthreads();

    // step 3: mv wuu1@u0 -> u1 ; stage wzu1
    stage(S.WB0, wzu1_w, tid);
    mvq4(S.WB1, S.u0, S.P, q, h, k0);
    __syncthreads();
    {
        float t = S.P[0][q][h] + S.P[1][q][h] + S.P[2][q][h] + S.P[3][q][h];
        S.u1[q][h] = softplus_f(t + wuu1_b[h]);
    }
    __syncthreads();

    // step 4: mv wzu1@u0 -> zur ; stage wyu1
    stage(S.WB1, wyu1_w, tid);
    mvq4(S.WB0, S.u0, S.P, q, h, k0);
    __syncthreads();
    {
        float t = S.P[0][q][h] + S.P[1][q][h] + S.P[2][q][h] + S.P[3][q][h];
        g_c[2][gi] = softplus_f(t + wzu1_b[h]);
    }
    __syncthreads();

    // step 5: mv wyu1@u0 -> a1 ; stage wu1
    stage(S.WB0, wu1_w, tid);
    mvq4(S.WB1, S.u0, S.P, q, h, k0);
    __syncthreads();
    g_c[3][gi] = S.P[0][q][h] + S.P[1][q][h] + S.P[2][q][h] + S.P[3][q][h] + wyu1_b[h];
    __syncthreads();

    // step 6: mv wu1@u0 -> c1 ; stage wyu2
    stage(S.WB1, wyu2_w, tid);
    mvq4(S.WB0, S.u0, S.P, q, h, k0);
    __syncthreads();
    g_c[4][gi] = S.P[0][q][h] + S.P[1][q][h] + S.P[2][q][h] + S.P[3][q][h] + wu1_b[h];
    __syncthreads();

    // step 7: mv wyu2@u1 -> a2w ; warps 12..15 compute zu2[s]
    mvq4(S.WB1, S.u1, S.P, q, h, k0);
    if (wr >= 12) {
        int ss = wr - 12;
        float4 wv = __ldg((const float4*)&wzu2_w[4 * l]);
        float4 uv = *(const float4*)&S.u1[ss][4 * l];
        float sv = wv.x*uv.x + wv.y*uv.y + wv.z*uv.z + wv.w*uv.w;
#pragma unroll
        for (int o = 16; o; o >>= 1)
            sv += __shfl_xor_sync(0xffffffffu, sv, o);
        if (l == 0) S.zu2[ss] = softplus_f(sv + wzu2_b[0]);
    }
    __syncthreads();
    {
        float t = S.P[0][q][h] + S.P[1][q][h] + S.P[2][q][h] + S.P[3][q][h];
        g_c[5][gi] = (t + wyu2_b[h]) * wy2[h];
        g_c[6][gi] = S.zu2[q] * fmaxf(wz2[h], 0.f);
    }
}

// ============================== main kernel ===============================

struct __align__(16) Smem {
    float Wy0[H * WST];       // fp32 rows (M1) + scalar cols (D)
    float WP[H * SP];         // interleaved (W1p, Wy1): rows (M2) + col float2 (C)
    float yv0[2][H];
    float yv1[2][H];
    float zz [2][H];
    float v2 [2][H];
    float v1 [2][H];
    float P1[4][PW];          // packed partials: [q][2h+s]
    float P2[4][PW];
    float red[8];
    int   flag;
};

__device__ __forceinline__ void spsig(float s, float& z, float& sg) {
    float e = __expf(s);
    float zz_ = __logf(1.f + e);
    float sgg = e / (1.f + e);
    if (s > 15.f) { zz_ = s; sgg = 1.f; }
    z = zz_; sg = sgg;
}

__global__ __launch_bounds__(NTHREADS, 1)
void pblnn_kernel(
    const float* __restrict__ y,
    const float* __restrict__ wy0,
    const float* __restrict__ wz1,
    const float* __restrict__ wy1,
    float* __restrict__ out)
{
    extern __shared__ char smem_raw[];
    Smem& S = *reinterpret_cast<Smem*>(smem_raw);

    const int tid  = threadIdx.x;
    const int lane = tid & 31;
    const int wrp  = tid >> 5;
    const int h    = tid & (H - 1);
    const int q    = tid >> 7;          // quarter 0..3
    const int k0   = q * 32;
    const bool act = (q < 2);           // elementwise lanes; s = q
    const int s    = q & 1;
    const int samp = blockIdx.x * 2;

    // ---- stage loop weights into smem ----
    for (int e = tid; e < H * H / 4; e += NTHREADS) {
        int r = e >> 5, c4 = (e & 31) * 4;
        *(float4*)&S.Wy0[r * WST + c4] = __ldg((const float4*)&wy0[r * H + c4]);
        float4 w1 = __ldg((const float4*)&wz1[r * H + c4]);
        w1.x = fmaxf(w1.x, 0.f); w1.y = fmaxf(w1.y, 0.f);
        w1.z = fmaxf(w1.z, 0.f); w1.w = fmaxf(w1.w, 0.f);
        float4 wy = __ldg((const float4*)&wy1[r * H + c4]);
        float4 lo = make_float4(w1.x, wy.x, w1.y, wy.y);
        float4 hi = make_float4(w1.z, wy.z, w1.w, wy.w);
        *(float4*)&S.WP[r * SP + 2 * c4]     = lo;
        *(float4*)&S.WP[r * SP + 2 * c4 + 4] = hi;
    }

    // ---- load per-sample constants from precompute scratch ----
    float a0r = 0.f, c0r = 0.f, zur = 0.f, a1r = 0.f, c1r = 0.f;
    float a2w = 0.f, vw2 = 0.f, yr = 0.f;
    float y1r = 1.f, yhist = 1.f, zs1r = 0.f, gAr = 0.f;
    if (act) {
        int gi = (samp + s) * H + h;
        a0r = g_c[0][gi];  c0r = g_c[1][gi];  zur = g_c[2][gi];
        a1r = g_c[3][gi];  c1r = g_c[4][gi];
        a2w = g_c[5][gi];  vw2 = g_c[6][gi];
        yr  = y[gi];
        S.yv0[s][h] = a0r;      // y1 = 1
        S.yv1[s][h] = a1r;
    }
    __syncthreads();            // weights + yv ready for iter 0

    // ---- fixed-point iterations: lag-2, atomic-free convergence pipeline ----
    int broke = 0;
    for (int it = 0; it < MAXIT; ++it) {
        // post residual of it-1: one plain volatile store, value doubles as flag
        if (tid == 416 && it > 0) {
            float n0 = sqrtf(S.red[0] + S.red[1] + S.red[2] + S.red[3]);
            float n1 = sqrtf(S.red[4] + S.red[5] + S.red[6] + S.red[7]);
            *((volatile float*)&g_part[(it - 1) * NCTA + blockIdx.x]) = n0 + n1;
        }
        // checker warp: cooperative poll + sum of lag-2 slots (overlaps M1)
        if (wrp == 12) {
            int f = 0;
            if (it >= 2) {
                volatile const float* gp = &g_part[(it - 2) * NCTA];
                float sum;
                for (;;) {
                    float v0 = gp[lane], v1 = gp[lane + 32];
                    float v2 = gp[lane + 64], v3 = gp[lane + 96];
                    bool ok = (v0 >= 0.f) & (v1 >= 0.f) & (v2 >= 0.f) & (v3 >= 0.f);
                    if (__all_sync(0xffffffffu, ok)) { sum = v0 + v1 + v2 + v3; break; }
                }
#pragma unroll
                for (int o = 16; o; o >>= 1)
                    sum += __shfl_xor_sync(0xffffffffu, sum, o);
                if (sum * (1.f / 256.f) < TOLF) f = 1;
            }
            if (lane == 0) S.flag = f;
        }

        // M1: s1 partial = Wy0[h][k0..k0+32) . yv0
        {
            const float4* W  = (const float4*)&S.Wy0[h * WST + k0];
            const float4* V0 = (const float4*)&S.yv0[0][k0];
            const float4* V1 = (const float4*)&S.yv0[1][k0];
            float m0a = 0.f, m0b = 0.f, m1a = 0.f, m1b = 0.f;
#pragma unroll
            for (int c = 0; c < 8; c += 2) {
                float4 w = W[c], a = V0[c], b = V1[c];
                m0a += w.x * a.x + w.y * a.y + w.z * a.z + w.w * a.w;
                m1a += w.x * b.x + w.y * b.y + w.z * b.z + w.w * b.w;
                float4 w2 = W[c + 1], a2 = V0[c + 1], b2 = V1[c + 1];
                m0b += w2.x * a2.x + w2.y * a2.y + w2.z * a2.z + w2.w * a2.w;
                m1b += w2.x * b2.x + w2.y * b2.y + w2.z * b2.z + w2.w * b2.w;
            }
            *(float2*)&S.P1[q][2 * h] = make_float2(m0a + m0b, m1a + m1b);
        }
        __syncthreads();                                   // #2

        // flag = conv(it-2), stable after #2; break BEFORE this iteration's update.
        if (S.flag) { broke = 1; break; }

        if (act) {
            int ix = 2 * h + s;
            float s1 = S.P1[0][ix] + S.P1[1][ix] + S.P1[2][ix] + S.P1[3][ix] + c0r;
            float z1, sg1;
            spsig(s1, z1, sg1);
            zs1r = sg1 * zur;
            S.zz[s][h] = z1 * zur;
        }
        __syncthreads();                                   // #3

        // M2: s2 partial = W1p@zz + Wy1@yv1 via packed WP rows
        {
            const float4* WA = (const float4*)&S.WP[h * SP + 2 * k0];
            const float4* Z0 = (const float4*)&S.zz[0][k0];
            const float4* Z1 = (const float4*)&S.zz[1][k0];
            const float4* Y0 = (const float4*)&S.yv1[0][k0];
            const float4* Y1 = (const float4*)&S.yv1[1][k0];
            float mA0 = 0.f, mA1 = 0.f, mB0 = 0.f, mB1 = 0.f;
#pragma unroll
            for (int c = 0; c < 8; c++) {
                float4 wlo = WA[2 * c];
                float4 whi = WA[2 * c + 1];
                float4 z0 = Z0[c], z1v = Z1[c], u0v = Y0[c], u1v = Y1[c];
                mA0 += wlo.x * z0.x + wlo.z * z0.y + whi.x * z0.z + whi.z * z0.w;
                mB0 += wlo.y * u0v.x + wlo.w * u0v.y + whi.y * u0v.z + whi.w * u0v.w;
                mA1 += wlo.x * z1v.x + wlo.z * z1v.y + whi.x * z1v.z + whi.z * z1v.w;
                mB1 += wlo.y * u1v.x + wlo.w * u1v.y + whi.y * u1v.z + whi.w * u1v.w;
            }
            *(float2*)&S.P1[q][2 * h] = make_float2(mA0 + mB0, mA1 + mB1);
        }
        __syncthreads();                                   // #4

        if (act) {
            int ix = 2 * h + s;
            float s2 = S.P1[0][ix] + S.P1[1][ix] + S.P1[2][ix] + S.P1[3][ix] + c1r;
            float sg2 = 1.f / (1.f + __expf(-s2));
            S.v2[s][h] = vw2 * sg2;
        }
        __syncthreads();                                   // #5

        // C: tv partial (W1p cols) + gA partial (Wy1 cols) via packed WP col float2
        {
            float tA0 = 0.f, tA1 = 0.f, gA0 = 0.f, gA1 = 0.f;
#pragma unroll
            for (int c = 0; c < 8; c++) {
                int kp = k0 + 4 * c;
                float4 a = *(const float4*)&S.v2[0][kp];
                float4 b = *(const float4*)&S.v2[1][kp];
#define STC(r, av, bv) { \
                float2 wc = *(const float2*)&S.WP[(kp + r) * SP + 2 * h]; \
                tA0 += (av) * wc.x;  tA1 += (bv) * wc.x; \
                gA0 += (av) * wc.y;  gA1 += (bv) * wc.y; }
                STC(0, a.x, b.x) STC(1, a.y, b.y) STC(2, a.z, b.z) STC(3, a.w, b.w)
#undef STC
            }
            *(float2*)&S.P1[q][2 * h] = make_float2(tA0, tA1);
            *(float2*)&S.P2[q][2 * h] = make_float2(gA0, gA1);
        }
        __syncthreads();                                   // #6

        if (act) {
            int ix = 2 * h + s;
            float tv = S.P1[0][ix] + S.P1[1][ix] + S.P1[2][ix] + S.P1[3][ix];
            gAr      = S.P2[0][ix] + S.P2[1][ix] + S.P2[2][ix] + S.P2[3][ix];
            S.v1[s][h] = tv * zs1r;
        }
        __syncthreads();                                   // #7

        // D: gB partial (Wy0 cols, scalar)
        {
            float g0 = 0.f, g1 = 0.f;
#pragma unroll
            for (int c = 0; c < 8; c++) {
                int kp = k0 + 4 * c;
                float4 a = *(const float4*)&S.v1[0][kp];
                float4 b = *(const float4*)&S.v1[1][kp];
#define STD(r, av, bv) { \
                float w = S.Wy0[(kp + r) * WST + h]; \
                g0 += (av) * w;  g1 += (bv) * w; }
                STD(0, a.x, b.x) STD(1, a.y, b.y) STD(2, a.z, b.z) STD(3, a.w, b.w)
#undef STD
            }
            *(float2*)&S.P1[q][2 * h] = make_float2(g0, g1);
        }
        __syncthreads();                                   // #8

        float rres = 0.f;
        if (act) {
            int ix = 2 * h + s;
            float gB = S.P1[0][ix] + S.P1[1][ix] + S.P1[2][ix] + S.P1[3][ix];
            float g = a1r * gAr + a0r * gB + a2w + 0.5f * y1r;
            rres = yr - g;
            float qq = rres * rres;
#pragma unroll
            for (int o = 16; o; o >>= 1)
                qq += __shfl_xor_sync(0xffffffffu, qq, o);
            if ((h & 31) == 0) S.red[tid >> 5] = qq;   // warps 0..7
        }

        if (act) {
            yhist = y1r;                       // y1_after(it-1)
            y1r += (4.f / (float)(it + 1)) * rres;
            S.yv0[s][h] = y1r * a0r;
            S.yv1[s][h] = y1r * a1r;
        }
        __syncthreads();     // #E: red/yv ready; flag not yet overwritten
    }
    if (broke && act) y1r = yhist;   // exact revert to y1_after(break_it - 2)

    // ---- output: mean over dims of (y1 + y) per sample ----
    float o = act ? (y1r + yr) : 0.f;
    if (act) {
#pragma unroll
        for (int off = 16; off; off >>= 1)
            o += __shfl_xor_sync(0xffffffffu, o, off);
        if ((h & 31) == 0) S.red[tid >> 5] = o;
    }
    __syncthreads();
    if (tid == 0) {
        out[samp]     = (S.red[0] + S.red[1] + S.red[2] + S.red[3]) * (1.f / 128.f);
        out[samp + 1] = (S.red[4] + S.red[5] + S.red[6] + S.red[7]) * (1.f / 128.f);
    }
}

extern "C" void kernel_launch(void* const* d_in, const int* in_sizes, int n_in,
                              void* d_out, int out_size) {
    (void)in_sizes; (void)n_in; (void)out_size;
    const float* x      = (const float*)d_in[0];
    const float* y      = (const float*)d_in[1];
    const float* wuu0_w = (const float*)d_in[2];
    const float* wuu0_b = (const float*)d_in[3];
    const float* wyu0_w = (const float*)d_in[4];
    const float* wyu0_b = (const float*)d_in[5];
    const float* wy0    = (const float*)d_in[6];
    const float* wu0_w  = (const float*)d_in[7];
    const float* wu0_b  = (const float*)d_in[8];
    const float* wuu1_w = (const float*)d_in[9];
    const float* wuu1_b = (const float*)d_in[10];
    const float* wzu1_w = (const float*)d_in[11];
    const float* wzu1_b = (const float*)d_in[12];
    const float* wz1    = (const float*)d_in[13];
    const float* wyu1_w = (const float*)d_in[14];
    const float* wyu1_b = (const float*)d_in[15];
    const float* wy1    = (const float*)d_in[16];
    const float* wu1_w  = (const float*)d_in[17];
    const float* wu1_b  = (const float*)d_in[18];
    const float* wzu2_w = (const float*)d_in[19];
    const float* wzu2_b = (const float*)d_in[20];
    const float* wz2    = (const float*)d_in[21];
    const float* wyu2_w = (const float*)d_in[22];
    const float* wyu2_b = (const float*)d_in[23];
    const float* wy2    = (const float*)d_in[24];
    // d_in[25] (wu2_w), d_in[26] (wu2_b) do not affect the gradient / output.

    size_t psmem = sizeof(PSmem);
    size_t smem  = sizeof(Smem);
    cudaFuncSetAttribute(pblnn_pre_kernel, cudaFuncAttributeMaxDynamicSharedMemorySize, (int)psmem);
    cudaFuncSetAttribute(pblnn_kernel, cudaFuncAttributeMaxDynamicSharedMemorySize, (int)smem);

    pblnn_pre_kernel<<<PCTA, 512, psmem>>>(
        x,
        wuu0_w, wuu0_b, wyu0_w, wyu0_b, wu0_w, wu0_b,
        wuu1_w, wuu1_b, wzu1_w, wzu1_b, wyu1_w, wyu1_b, wu1_w, wu1_b,
        wzu2_w, wzu2_b, wz2, wyu2_w, wyu2_b, wy2);
    pblnn_kernel<<<NCTA, NTHREADS, smem>>>(y, wy0, wz1, wy1, (float*)d_out);
}

// round 15
// speedup vs baseline: 1.0637x; 1.0637x over previous
#include <cuda_runtime.h>
#include <math.h>

#define H        128
#define WST      132      // fp32 stride: 132 % 32 == 4 -> conflict-free row+col access
#define SP       260      // packed float2 matrix stride (260 % 32 == 4)
#define PW       (2 * H + 8)
#define NCTA     128
#define NTHREADS 512
#define MAXIT    500
#define TOLF     1e-3f

// per-(iteration, CTA) residual slots; -1 = not posted, >=0 = posted value.
// Self-initialized at kernel start (each CTA resets its own 512 slots; the
// earliest cross-CTA read is >= 2 iterations later, far beyond launch skew).
__device__ float g_part[NCTA * NTHREADS];   // 65536 >= MAXIT*NCTA

struct __align__(16) Smem {
    float Wy0[H * WST];       // staging buffer A -> final Wy0 (rows M1 + cols D)
    float WP[H * SP];         // staging buffer B (first H*WST) -> final packed (W1p,Wy1)
    float yv0[2][H];
    float yv1[2][H];
    float zz [2][H];          // precompute: u1
    float v2 [2][H];          // precompute: x
    float v1 [2][H];          // precompute: u0
    float P1[4][PW];          // packed partials: [q][2h+s]
    float P2[4][PW];
    float red[8];
    float zu2[2];
    int   flag;
};

__device__ __forceinline__ float softplus_f(float s) {
    float e = __expf(s);
    float z = __logf(1.f + e);
    return (s > 15.f) ? s : z;
}

__device__ __forceinline__ void spsig(float s, float& z, float& sg) {
    float e = __expf(s);
    float zz_ = __logf(1.f + e);
    float sgg = e / (1.f + e);
    if (s > 15.f) { zz_ = s; sgg = 1.f; }
    z = zz_; sg = sgg;
}

// coalesced stage: one H x H gmem matrix -> smem (stride WST)
__device__ __forceinline__ void stage(float* dst, const float* __restrict__ w, int tid) {
#pragma unroll
    for (int i = 0; i < 8; i++) {
        int e = tid + i * 512;
        int r = e >> 5, c4 = (e & 31) * 4;
        *(float4*)&dst[r * WST + c4] = __ldg((const float4*)&w[r * H + c4]);
    }
}

// quarter matvec (2 samples) out of a WST-stride smem matrix -> packed P1
__device__ __forceinline__ void mvstep(const float* Wb, const float* v0, const float* v1,
                                       float* P1q, int h, int k0) {
    const float4* W  = (const float4*)&Wb[h * WST + k0];
    const float4* V0 = (const float4*)&v0[k0];
    const float4* V1 = (const float4*)&v1[k0];
    float m0a = 0.f, m0b = 0.f, m1a = 0.f, m1b = 0.f;
#pragma unroll
    for (int c = 0; c < 8; c += 2) {
        float4 w = W[c], a = V0[c], b = V1[c];
        m0a += w.x * a.x + w.y * a.y + w.z * a.z + w.w * a.w;
        m1a += w.x * b.x + w.y * b.y + w.z * b.z + w.w * b.w;
        float4 w2 = W[c + 1], a2 = V0[c + 1], b2 = V1[c + 1];
        m0b += w2.x * a2.x + w2.y * a2.y + w2.z * a2.z + w2.w * a2.w;
        m1b += w2.x * b2.x + w2.y * b2.y + w2.z * b2.z + w2.w * b2.w;
    }
    *(float2*)&P1q[2 * h] = make_float2(m0a + m0b, m1a + m1b);
}

__global__ __launch_bounds__(NTHREADS, 1)
void pblnn_kernel(
    const float* __restrict__ x,      const float* __restrict__ y,
    const float* __restrict__ wuu0_w, const float* __restrict__ wuu0_b,
    const float* __restrict__ wyu0_w, const float* __restrict__ wyu0_b,
    const float* __restrict__ wy0,
    const float* __restrict__ wu0_w,  const float* __restrict__ wu0_b,
    const float* __restrict__ wuu1_w, const float* __restrict__ wuu1_b,
    const float* __restrict__ wzu1_w, const float* __restrict__ wzu1_b,
    const float* __restrict__ wz1,
    const float* __restrict__ wyu1_w, const float* __restrict__ wyu1_b,
    const float* __restrict__ wy1,
    const float* __restrict__ wu1_w,  const float* __restrict__ wu1_b,
    const float* __restrict__ wzu2_w, const float* __restrict__ wzu2_b,
    const float* __restrict__ wz2,
    const float* __restrict__ wyu2_w, const float* __restrict__ wyu2_b,
    const float* __restrict__ wy2,
    float* __restrict__ out)
{
    extern __shared__ char smem_raw[];
    Smem& S = *reinterpret_cast<Smem*>(smem_raw);

    const int tid  = threadIdx.x;
    const int lane = tid & 31;
    const int wrp  = tid >> 5;
    const int h    = tid & (H - 1);
    const int q    = tid >> 7;          // quarter 0..3
    const int k0   = q * 32;
    const bool act = (q < 2);           // elementwise lanes; s = q
    const int s    = q & 1;
    const int samp = blockIdx.x * 2;

    float* bufA = S.Wy0;
    float* bufB = S.WP;                 // first H*WST floats of WP region

    // reset this CTA's residual slots (NCTA*NTHREADS covers all of g_part)
    g_part[blockIdx.x * NTHREADS + tid] = -1.f;

    // ---- fused precompute: coalesced double-buffered staging ----
    if (tid < 2 * H) S.v2[tid >> 7][tid & 127] = x[samp * H + tid];   // xv
    stage(bufA, wuu0_w, tid);
    __syncthreads();

    float a0r = 0.f, c0r = 0.f, zur = 0.f, a1r = 0.f, c1r = 0.f;
    float a2w = 0.f, vw2 = 0.f, yr = 0.f;
    float y1r = 1.f, yhist = 1.f, zs1r = 0.f, gAr = 0.f;
    const int ix = 2 * h + s;

    // step 0: mv wuu0@x (A) ; stage wyu0 -> B
    stage(bufB, wyu0_w, tid);
    mvstep(bufA, S.v2[0], S.v2[1], S.P1[q], h, k0);
    __syncthreads();
    if (act) {
        float t = S.P1[0][ix] + S.P1[1][ix] + S.P1[2][ix] + S.P1[3][ix];
        S.v1[s][h] = softplus_f(t + __ldg(&wuu0_b[h]));      // u0
    }
    __syncthreads();

    // step 1: mv wyu0@x (B) ; stage wu0 -> A
    stage(bufA, wu0_w, tid);
    mvstep(bufB, S.v2[0], S.v2[1], S.P1[q], h, k0);
    __syncthreads();
    if (act)
        a0r = S.P1[0][ix] + S.P1[1][ix] + S.P1[2][ix] + S.P1[3][ix] + __ldg(&wyu0_b[h]);
    __syncthreads();

    // step 2: mv wu0@x (A) ; stage wuu1 -> B
    stage(bufB, wuu1_w, tid);
    mvstep(bufA, S.v2[0], S.v2[1], S.P1[q], h, k0);
    __syncthreads();
    if (act)
        c0r = S.P1[0][ix] + S.P1[1][ix] + S.P1[2][ix] + S.P1[3][ix] + __ldg(&wu0_b[h]);
    __syncthreads();

    // step 3: mv wuu1@u0 (B) ; stage wzu1 -> A
    stage(bufA, wzu1_w, tid);
    mvstep(bufB, S.v1[0], S.v1[1], S.P1[q], h, k0);
    __syncthreads();
    if (act) {
        float t = S.P1[0][ix] + S.P1[1][ix] + S.P1[2][ix] + S.P1[3][ix];
        S.zz[s][h] = softplus_f(t + __ldg(&wuu1_b[h]));      // u1
    }
    __syncthreads();

    // step 4: mv wzu1@u0 (A) ; stage wyu1 -> B
    stage(bufB, wyu1_w, tid);
    mvstep(bufA, S.v1[0], S.v1[1], S.P1[q], h, k0);
    __syncthreads();
    if (act) {
        float t = S.P1[0][ix] + S.P1[1][ix] + S.P1[2][ix] + S.P1[3][ix];
        zur = softplus_f(t + __ldg(&wzu1_b[h]));
    }
    __syncthreads();

    // step 5: mv wyu1@u0 (B) ; stage wu1 -> A
    stage(bufA, wu1_w, tid);
    mvstep(bufB, S.v1[0], S.v1[1], S.P1[q], h, k0);
    __syncthreads();
    if (act)
        a1r = S.P1[0][ix] + S.P1[1][ix] + S.P1[2][ix] + S.P1[3][ix] + __ldg(&wyu1_b[h]);
    __syncthreads();

    // step 6: mv wu1@u0 (A) ; stage wyu2 -> B
    stage(bufB, wyu2_w, tid);
    mvstep(bufA, S.v1[0], S.v1[1], S.P1[q], h, k0);
    __syncthreads();
    if (act)
        c1r = S.P1[0][ix] + S.P1[1][ix] + S.P1[2][ix] + S.P1[3][ix] + __ldg(&wu1_b[h]);
    __syncthreads();

    // step 7: mv wyu2@u1 (B) ; stage FINAL Wy0 -> A (= S.Wy0) ; zu2 by warps 14/15
    stage(bufA, wy0, tid);
    mvstep(bufB, S.zz[0], S.zz[1], S.P1[q], h, k0);
    if (wrp >= 14) {
        int ss = wrp - 14;
        float4 wv = __ldg((const float4*)&wzu2_w[4 * lane]);
        float4 uv = *(const float4*)&S.zz[ss][4 * lane];
        float sv = wv.x*uv.x + wv.y*uv.y + wv.z*uv.z + wv.w*uv.w;
#pragma unroll
        for (int o = 16; o; o >>= 1)
            sv += __shfl_xor_sync(0xffffffffu, sv, o);
        if (lane == 0) S.zu2[ss] = softplus_f(sv + __ldg(&wzu2_b[0]));
    }
    __syncthreads();
    if (act) {
        float t = S.P1[0][ix] + S.P1[1][ix] + S.P1[2][ix] + S.P1[3][ix];
        a2w = (t + __ldg(&wyu2_b[h])) * __ldg(&wy2[h]);
        vw2 = S.zu2[s] * fmaxf(__ldg(&wz2[h]), 0.f);
    }
    __syncthreads();

    // step 8: stage FINAL packed WP (relu(wz1), wy1) ; init loop state
    for (int e = tid; e < H * H / 4; e += NTHREADS) {
        int r = e >> 5, c4 = (e & 31) * 4;
        float4 w1 = __ldg((const float4*)&wz1[r * H + c4]);
        w1.x = fmaxf(w1.x, 0.f); w1.y = fmaxf(w1.y, 0.f);
        w1.z = fmaxf(w1.z, 0.f); w1.w = fmaxf(w1.w, 0.f);
        float4 wy = __ldg((const float4*)&wy1[r * H + c4]);
        float4 lo = make_float4(w1.x, wy.x, w1.y, wy.y);
        float4 hi = make_float4(w1.z, wy.z, w1.w, wy.w);
        *(float4*)&S.WP[r * SP + 2 * c4]     = lo;
        *(float4*)&S.WP[r * SP + 2 * c4 + 4] = hi;
    }
    if (act) {
        yr = y[(samp + s) * H + h];
        S.yv0[s][h] = a0r;      // y1 = 1
        S.yv1[s][h] = a1r;
    }
    __syncthreads();            // weights + yv ready for iter 0

    // ---- fixed-point iterations: lag-2, atomic-free convergence pipeline ----
    int broke = 0;
    for (int it = 0; it < MAXIT; ++it) {
        // post residual of it-1: one plain volatile store, value doubles as flag
        if (tid == 416 && it > 0) {
            float n0 = sqrtf(S.red[0] + S.red[1] + S.red[2] + S.red[3]);
            float n1 = sqrtf(S.red[4] + S.red[5] + S.red[6] + S.red[7]);
            *((volatile float*)&g_part[(it - 1) * NCTA + blockIdx.x]) = n0 + n1;
        }
        // checker warp: cooperative poll + sum of lag-2 slots (overlaps M1)
        if (wrp == 12) {
            int f = 0;
            if (it >= 2) {
                volatile const float* gp = &g_part[(it - 2) * NCTA];
                float sum;
                for (;;) {
                    float v0 = gp[lane], v1 = gp[lane + 32];
                    float v2 = gp[lane + 64], v3 = gp[lane + 96];
                    bool ok = (v0 >= 0.f) & (v1 >= 0.f) & (v2 >= 0.f) & (v3 >= 0.f);
                    if (__all_sync(0xffffffffu, ok)) { sum = v0 + v1 + v2 + v3; break; }
                }
#pragma unroll
                for (int o = 16; o; o >>= 1)
                    sum += __shfl_xor_sync(0xffffffffu, sum, o);
                if (sum * (1.f / 256.f) < TOLF) f = 1;
            }
            if (lane == 0) S.flag = f;
        }

        // M1: s1 partial = Wy0[h][k0..k0+32) . yv0
        mvstep(S.Wy0, S.yv0[0], S.yv0[1], S.P1[q], h, k0);
        __syncthreads();                                   // #2

        // flag = conv(it-2), stable after #2; break BEFORE this iteration's update.
        if (S.flag) { broke = 1; break; }

        if (act) {
            float s1 = S.P1[0][ix] + S.P1[1][ix] + S.P1[2][ix] + S.P1[3][ix] + c0r;
            float z1, sg1;
            spsig(s1, z1, sg1);
            zs1r = sg1 * zur;
            S.zz[s][h] = z1 * zur;
        }
        __syncthreads();                                   // #3

        // M2: s2 partial = W1p@zz + Wy1@yv1 via packed WP rows
        {
            const float4* WA = (const float4*)&S.WP[h * SP + 2 * k0];
            const float4* Z0 = (const float4*)&S.zz[0][k0];
            const float4* Z1 = (const float4*)&S.zz[1][k0];
            const float4* Y0 = (const float4*)&S.yv1[0][k0];
            const float4* Y1 = (const float4*)&S.yv1[1][k0];
            float mA0 = 0.f, mA1 = 0.f, mB0 = 0.f, mB1 = 0.f;
#pragma unroll
            for (int c = 0; c < 8; c++) {
                float4 wlo = WA[2 * c];
                float4 whi = WA[2 * c + 1];
                float4 z0 = Z0[c], z1v = Z1[c], u0v = Y0[c], u1v = Y1[c];
                mA0 += wlo.x * z0.x + wlo.z * z0.y + whi.x * z0.z + whi.z * z0.w;
                mB0 += wlo.y * u0v.x + wlo.w * u0v.y + whi.y * u0v.z + whi.w * u0v.w;
                mA1 += wlo.x * z1v.x + wlo.z * z1v.y + whi.x * z1v.z + whi.z * z1v.w;
                mB1 += wlo.y * u1v.x + wlo.w * u1v.y + whi.y * u1v.z + whi.w * u1v.w;
            }
            *(float2*)&S.P1[q][2 * h] = make_float2(mA0 + mB0, mA1 + mB1);
        }
        __syncthreads();                                   // #4

        if (act) {
            float s2 = S.P1[0][ix] + S.P1[1][ix] + S.P1[2][ix] + S.P1[3][ix] + c1r;
            float sg2 = 1.f / (1.f + __expf(-s2));
            S.v2[s][h] = vw2 * sg2;
        }
        __syncthreads();                                   // #5

        // C: tv partial (W1p cols) + gA partial (Wy1 cols) via packed WP col float2
        {
            float tA0 = 0.f, tA1 = 0.f, gA0 = 0.f, gA1 = 0.f;
#pragma unroll
            for (int c = 0; c < 8; c++) {
                int kp = k0 + 4 * c;
                float4 a = *(const float4*)&S.v2[0][kp];
                float4 b = *(const float4*)&S.v2[1][kp];
#define STC(r, av, bv) { \
                float2 wc = *(const float2*)&S.WP[(kp + r) * SP + 2 * h]; \
                tA0 += (av) * wc.x;  tA1 += (bv) * wc.x; \
                gA0 += (av) * wc.y;  gA1 += (bv) * wc.y; }
                STC(0, a.x, b.x) STC(1, a.y, b.y) STC(2, a.z, b.z) STC(3, a.w, b.w)
#undef STC
            }
            *(float2*)&S.P1[q][2 * h] = make_float2(tA0, tA1);
            *(float2*)&S.P2[q][2 * h] = make_float2(gA0, gA1);
        }
        __syncthreads();                                   // #6

        if (act) {
            float tv = S.P1[0][ix] + S.P1[1][ix] + S.P1[2][ix] + S.P1[3][ix];
            gAr      = S.P2[0][ix] + S.P2[1][ix] + S.P2[2][ix] + S.P2[3][ix];
            S.v1[s][h] = tv * zs1r;
        }
        __syncthreads();                                   // #7

        // D: gB partial (Wy0 cols, scalar)
        {
            float g0 = 0.f, g1 = 0.f;
#pragma unroll
            for (int c = 0; c < 8; c++) {
                int kp = k0 + 4 * c;
                float4 a = *(const float4*)&S.v1[0][kp];
                float4 b = *(const float4*)&S.v1[1][kp];
#define STD(r, av, bv) { \
                float w = S.Wy0[(kp + r) * WST + h]; \
                g0 += (av) * w;  g1 += (bv) * w; }
                STD(0, a.x, b.x) STD(1, a.y, b.y) STD(2, a.z, b.z) STD(3, a.w, b.w)
#undef STD
            }
            *(float2*)&S.P1[q][2 * h] = make_float2(g0, g1);
        }
        __syncthreads();                                   // #8

        float rres = 0.f;
        if (act) {
            float gB = S.P1[0][ix] + S.P1[1][ix] + S.P1[2][ix] + S.P1[3][ix];
            float g = a1r * gAr + a0r * gB + a2w + 0.5f * y1r;
            rres = yr - g;
            float qq = rres * rres;
#pragma unroll
            for (int o = 16; o; o >>= 1)
                qq += __shfl_xor_sync(0xffffffffu, qq, o);
            if ((h & 31) == 0) S.red[tid >> 5] = qq;   // warps 0..7
        }

        if (act) {
            yhist = y1r;                       // y1_after(it-1)
            y1r += (4.f / (float)(it + 1)) * rres;
            S.yv0[s][h] = y1r * a0r;
            S.yv1[s][h] = y1r * a1r;
        }
        __syncthreads();     // #E: red/yv ready; flag not yet overwritten
    }
    if (broke && act) y1r = yhist;   // exact revert to y1_after(break_it - 2)

    // ---- output: mean over dims of (y1 + y) per sample ----
    float o = act ? (y1r + yr) : 0.f;
    if (act) {
#pragma unroll
        for (int off = 16; off; off >>= 1)
            o += __shfl_xor_sync(0xffffffffu, o, off);
        if ((h & 31) == 0) S.red[tid >> 5] = o;
    }
    __syncthreads();
    if (tid == 0) {
        out[samp]     = (S.red[0] + S.red[1] + S.red[2] + S.red[3]) * (1.f / 128.f);
        out[samp + 1] = (S.red[4] + S.red[5] + S.red[6] + S.red[7]) * (1.f / 128.f);
    }
}

extern "C" void kernel_launch(void* const* d_in, const int* in_sizes, int n_in,
                              void* d_out, int out_size) {
    (void)in_sizes; (void)n_in; (void)out_size;
    const float* x      = (const float*)d_in[0];
    const float* y      = (const float*)d_in[1];
    const float* wuu0_w = (const float*)d_in[2];
    const float* wuu0_b = (const float*)d_in[3];
    const float* wyu0_w = (const float*)d_in[4];
    const float* wyu0_b = (const float*)d_in[5];
    const float* wy0    = (const float*)d_in[6];
    const float* wu0_w  = (const float*)d_in[7];
    const float* wu0_b  = (const float*)d_in[8];
    const float* wuu1_w = (const float*)d_in[9];
    const float* wuu1_b = (const float*)d_in[10];
    const float* wzu1_w = (const float*)d_in[11];
    const float* wzu1_b = (const float*)d_in[12];
    const float* wz1    = (const float*)d_in[13];
    const float* wyu1_w = (const float*)d_in[14];
    const float* wyu1_b = (const float*)d_in[15];
    const float* wy1    = (const float*)d_in[16];
    const float* wu1_w  = (const float*)d_in[17];
    const float* wu1_b  = (const float*)d_in[18];
    const float* wzu2_w = (const float*)d_in[19];
    const float* wzu2_b = (const float*)d_in[20];
    const float* wz2    = (const float*)d_in[21];
    const float* wyu2_w = (const float*)d_in[22];
    const float* wyu2_b = (const float*)d_in[23];
    const float* wy2    = (const float*)d_in[24];
    // d_in[25] (wu2_w), d_in[26] (wu2_b) do not affect the gradient / output.

    size_t smem = sizeof(Smem);
    cudaFuncSetAttribute(pblnn_kernel, cudaFuncAttributeMaxDynamicSharedMemorySize, (int)smem);

    pblnn_kernel<<<NCTA, NTHREADS, smem>>>(
        x, y,
        wuu0_w, wuu0_b, wyu0_w, wyu0_b, wy0, wu0_w, wu0_b,
        wuu1_w, wuu1_b, wzu1_w, wzu1_b, wz1, wyu1_w, wyu1_b, wy1, wu1_w, wu1_b,
        wzu2_w, wzu2_b, wz2, wyu2_w, wyu2_b, wy2,
        (float*)d_out);
}